// round 1
// baseline (speedup 1.0000x reference)
#include <cuda_runtime.h>
#include <math.h>

#define NN 50000
#define D  128
#define H2 256

// ---------------- scratch (no allocations allowed) ----------------
__device__ float g_agg1[NN * D];   // layer1 aggregation (128-wide)
__device__ float g_l1 [NN * H2];   // layer1 output (256-wide)
__device__ float g_m  [NN * D];    // (l1 * ns) @ W2  (pre-aggregation matmul)
__device__ float g_agg2[NN * D];   // layer2 aggregation (128-wide)
__device__ float g_h  [NN * D];    // encoder output
__device__ float g_z  [NN * D];    // elu(fc1) intermediate
__device__ float g_ns [NN];        // rsqrt(max(deg_out,1))
__device__ float g_nd [NN];        // rsqrt(max(deg_in ,1))
__device__ int   g_dego[NN];
__device__ int   g_degi[NN];

// ---------------- zero scratch for one graph ----------------
__global__ void k_zero() {
    int stride = gridDim.x * blockDim.x;
    int i0 = blockIdx.x * blockDim.x + threadIdx.x;
    float4 z4 = make_float4(0.f, 0.f, 0.f, 0.f);
    float4* a1 = (float4*)g_agg1;
    float4* a2 = (float4*)g_agg2;
    const int n4 = NN * D / 4;
    for (int i = i0; i < n4; i += stride) { a1[i] = z4; a2[i] = z4; }
    for (int i = i0; i < NN; i += stride) { g_dego[i] = 0; g_degi[i] = 0; }
}

// ---------------- degree counting ----------------
__global__ void k_deg(const int* __restrict__ src, const int* __restrict__ dst, int E) {
    int e = blockIdx.x * blockDim.x + threadIdx.x;
    if (e < E) {
        atomicAdd(&g_dego[src[e]], 1);
        atomicAdd(&g_degi[dst[e]], 1);
    }
}

__global__ void k_norm() {
    int i = blockIdx.x * blockDim.x + threadIdx.x;
    if (i < NN) {
        g_ns[i] = rsqrtf(fmaxf((float)g_dego[i], 1.f));
        g_nd[i] = rsqrtf(fmaxf((float)g_degi[i], 1.f));
    }
}

// ---------------- edge scatter: out[dst] += X[src] (*norm_src) ----------------
// one warp per edge, 4 floats per lane, float4 vector atomics (sm_90+)
template<bool SCALE>
__global__ void k_scatter(const float* __restrict__ X, const int* __restrict__ src,
                          const int* __restrict__ dst, float* __restrict__ out, int E) {
    int w = (int)((blockIdx.x * blockDim.x + threadIdx.x) >> 5);
    if (w >= E) return;
    int lane = threadIdx.x & 31;
    int s = __ldg(src + w);
    int d = __ldg(dst + w);
    float4 v = *(const float4*)(X + (size_t)s * D + lane * 4);
    if (SCALE) {
        float f = g_ns[s];
        v.x *= f; v.y *= f; v.z *= f; v.w *= f;
    }
    atomicAdd((float4*)(out + (size_t)d * D + lane * 4), v);
}

// ---------------- elementwise: h = relu(agg * nd[row] + bias[col]) ----------------
__global__ void k_post(const float* __restrict__ agg, const float* __restrict__ bias,
                       float* __restrict__ out) {
    int i = blockIdx.x * blockDim.x + threadIdx.x;  // over NN * (D/4)
    if (i >= NN * (D / 4)) return;
    int r  = i >> 5;          // D/4 = 32 float4 per row
    int c4 = (i & 31) * 4;
    float nd = g_nd[r];
    float4 a = ((const float4*)agg)[i];
    float4 b = *(const float4*)(bias + c4);
    float4 o;
    o.x = fmaxf(fmaf(a.x, nd, b.x), 0.f);
    o.y = fmaxf(fmaf(a.y, nd, b.y), 0.f);
    o.z = fmaxf(fmaf(a.z, nd, b.z), 0.f);
    o.w = fmaxf(fmaf(a.w, nd, b.w), 0.f);
    ((float4*)out)[i] = o;
}

// ---------------- fp32 SIMT GEMM, 128x128 tile, 8x8 microtile ----------------
// C[M,Nc] = act( (A(*arows) @ B) * erows + bias )
// ACT: 0=none, 1=relu, 2=elu
template<int ACT, bool ASCALE, bool EPISCALE, bool BIAS>
__global__ void __launch_bounds__(256) k_gemm(
    const float* __restrict__ A, const float* __restrict__ B, float* __restrict__ C,
    int M, int K, int Nc,
    const float* __restrict__ arows, const float* __restrict__ erows,
    const float* __restrict__ bias)
{
    __shared__ float As[8][128];
    __shared__ float Bs[8][128];
    int tid = threadIdx.x;
    int tx = tid & 15, ty = tid >> 4;
    int bm = blockIdx.y * 128;
    int bn = blockIdx.x * 128;

    float acc[8][8];
    #pragma unroll
    for (int i = 0; i < 8; i++)
        #pragma unroll
        for (int j = 0; j < 8; j++) acc[i][j] = 0.f;

    // A tile load mapping: 128 rows x 8 cols, one float4 per thread
    int arow = tid >> 1;
    int aseg = (tid & 1) * 4;
    int gar = bm + arow;
    float ascale = 1.f;
    if (ASCALE) ascale = (gar < M) ? arows[gar] : 0.f;
    const float* Aptr = A + (size_t)gar * K + aseg;
    // B tile load mapping: 8 rows x 128 cols, one float4 per thread
    int brow = tid >> 5;
    int bcol = (tid & 31) * 4;
    const float* Bptr = B + (size_t)brow * Nc + bn + bcol;

    for (int k0 = 0; k0 < K; k0 += 8) {
        float4 av = make_float4(0.f, 0.f, 0.f, 0.f);
        if (gar < M) av = *(const float4*)(Aptr + k0);
        if (ASCALE) { av.x *= ascale; av.y *= ascale; av.z *= ascale; av.w *= ascale; }
        float4 bv = *(const float4*)(Bptr + (size_t)k0 * Nc);

        As[aseg + 0][arow] = av.x;
        As[aseg + 1][arow] = av.y;
        As[aseg + 2][arow] = av.z;
        As[aseg + 3][arow] = av.w;
        *(float4*)&Bs[brow][bcol] = bv;
        __syncthreads();

        #pragma unroll
        for (int kk = 0; kk < 8; kk++) {
            float4 a0 = *(const float4*)&As[kk][ty * 8];
            float4 a1 = *(const float4*)&As[kk][ty * 8 + 4];
            float4 b0 = *(const float4*)&Bs[kk][tx * 8];
            float4 b1 = *(const float4*)&Bs[kk][tx * 8 + 4];
            float a[8] = {a0.x, a0.y, a0.z, a0.w, a1.x, a1.y, a1.z, a1.w};
            float b[8] = {b0.x, b0.y, b0.z, b0.w, b1.x, b1.y, b1.z, b1.w};
            #pragma unroll
            for (int i = 0; i < 8; i++)
                #pragma unroll
                for (int j = 0; j < 8; j++)
                    acc[i][j] = fmaf(a[i], b[j], acc[i][j]);
        }
        __syncthreads();
    }

    // epilogue
    #pragma unroll
    for (int i = 0; i < 8; i++) {
        int r = bm + ty * 8 + i;
        if (r >= M) break;
        float es = EPISCALE ? erows[r] : 1.f;
        #pragma unroll
        for (int j = 0; j < 8; j += 4) {
            int c = bn + tx * 8 + j;
            float4 o;
            o.x = acc[i][j + 0] * es;
            o.y = acc[i][j + 1] * es;
            o.z = acc[i][j + 2] * es;
            o.w = acc[i][j + 3] * es;
            if (BIAS) {
                o.x += bias[c + 0]; o.y += bias[c + 1];
                o.z += bias[c + 2]; o.w += bias[c + 3];
            }
            if (ACT == 1) {
                o.x = fmaxf(o.x, 0.f); o.y = fmaxf(o.y, 0.f);
                o.z = fmaxf(o.z, 0.f); o.w = fmaxf(o.w, 0.f);
            } else if (ACT == 2) {
                o.x = (o.x > 0.f) ? o.x : expm1f(o.x);
                o.y = (o.y > 0.f) ? o.y : expm1f(o.y);
                o.z = (o.z > 0.f) ? o.z : expm1f(o.z);
                o.w = (o.w > 0.f) ? o.w : expm1f(o.w);
            }
            *(float4*)(C + (size_t)r * Nc + c) = o;
        }
    }
}

// ---------------- driver ----------------
extern "C" void kernel_launch(void* const* d_in, const int* in_sizes, int n_in,
                              void* d_out, int out_size) {
    const float* feat1 = (const float*)d_in[0];
    const float* feat2 = (const float*)d_in[1];
    const int*   ei1   = (const int*)d_in[2];
    const int*   ei2   = (const int*)d_in[3];
    const float* W1    = (const float*)d_in[4];
    const float* b1    = (const float*)d_in[5];
    const float* W2    = (const float*)d_in[6];
    const float* b2    = (const float*)d_in[7];
    const float* f1W   = (const float*)d_in[8];
    const float* f1b   = (const float*)d_in[9];
    const float* f2W   = (const float*)d_in[10];
    const float* f2b   = (const float*)d_in[11];
    int E1 = in_sizes[2] / 2;
    int E2 = in_sizes[3] / 2;
    float* out = (float*)d_out;

    float *agg1, *l1, *m, *agg2, *h, *z, *ns, *nd;
    cudaGetSymbolAddress((void**)&agg1, g_agg1);
    cudaGetSymbolAddress((void**)&l1,   g_l1);
    cudaGetSymbolAddress((void**)&m,    g_m);
    cudaGetSymbolAddress((void**)&agg2, g_agg2);
    cudaGetSymbolAddress((void**)&h,    g_h);
    cudaGetSymbolAddress((void**)&z,    g_z);
    cudaGetSymbolAddress((void**)&ns,   g_ns);
    cudaGetSymbolAddress((void**)&nd,   g_nd);

    dim3 blk(256);
    int mtiles = (NN + 127) / 128;

    for (int g = 0; g < 2; g++) {
        const float* feat = g ? feat2 : feat1;
        const int*   ei   = g ? ei2 : ei1;
        int E = g ? E2 : E1;
        const int* src = ei;
        const int* dst = ei + E;
        float* outg = out + (size_t)g * NN * D;

        k_zero<<<2048, 256>>>();
        k_deg<<<(E + 255) / 256, 256>>>(src, dst, E);
        k_norm<<<(NN + 255) / 256, 256>>>();

        // layer 1: agg1[dst] += feat[src] * ns[src]
        k_scatter<true><<<(E * 32 + 255) / 256, 256>>>(feat, src, dst, agg1, E);
        // l1 = relu((agg1 @ W1) * nd + b1)   [M=N, K=128, Nc=256]
        k_gemm<1, false, true, true><<<dim3(2, mtiles), blk>>>(
            agg1, W1, l1, NN, 128, 256, nullptr, nd, b1);

        // layer 2 (matmul-before-scatter): m = (l1 * ns) @ W2   [K=256, Nc=128]
        k_gemm<0, true, false, false><<<dim3(1, mtiles), blk>>>(
            l1, W2, m, NN, 256, 128, ns, nullptr, nullptr);
        // agg2[dst] += m[src]
        k_scatter<false><<<(E * 32 + 255) / 256, 256>>>(m, src, dst, agg2, E);
        // h = relu(agg2 * nd + b2)
        k_post<<<(NN * 32 + 255) / 256, 256>>>(agg2, b2, h);

        // projection MLP
        k_gemm<2, false, false, true><<<dim3(1, mtiles), blk>>>(
            h, f1W, z, NN, 128, 128, nullptr, nullptr, f1b);
        k_gemm<0, false, false, true><<<dim3(1, mtiles), blk>>>(
            z, f2W, outg, NN, 128, 128, nullptr, nullptr, f2b);
    }
}

// round 3
// speedup vs baseline: 1.6745x; 1.6745x over previous
#include <cuda_runtime.h>
#include <math.h>
#include <stdint.h>

#define NN 50000
#define D  128
#define H2 256

// ---------------- scratch (no allocations allowed) ----------------
__device__ float g_agg1[NN * D];
__device__ float g_l1 [NN * H2];
__device__ float g_m  [NN * D];
__device__ float g_agg2[NN * D];
__device__ float g_h  [NN * D];
__device__ float g_z  [NN * D];
__device__ float g_ns [NN];
__device__ float g_nd [NN];
__device__ int   g_dego[NN];
__device__ int   g_degi[NN];
// transposed ([N,K] row-major) + tf32-rounded weights
__device__ float g_Wt1[256 * 128];
__device__ float g_Wt2[128 * 256];
__device__ float g_Wt3[128 * 128];
__device__ float g_Wt4[128 * 128];

// ---------------- helpers ----------------
__device__ __forceinline__ uint32_t smem_u32(const void* p) {
    uint32_t a;
    asm("{ .reg .u64 t; cvta.to.shared.u64 t, %1; cvt.u32.u64 %0, t; }" : "=r"(a) : "l"(p));
    return a;
}
__device__ __forceinline__ float tf32r(float x) {
    uint32_t u;
    asm("cvt.rna.tf32.f32 %0, %1;" : "=r"(u) : "f"(x));
    return __uint_as_float(u);
}
__device__ __forceinline__ void cpasync16(uint32_t saddr, const void* gaddr, bool pred) {
    int sz = pred ? 16 : 0;
    asm volatile("cp.async.ca.shared.global [%0], [%1], 16, %2;"
                 :: "r"(saddr), "l"(gaddr), "r"(sz) : "memory");
}
__device__ __forceinline__ void cp_commit() {
    asm volatile("cp.async.commit_group;" ::: "memory");
}
__device__ __forceinline__ void mma_tf32(float* c, const uint32_t* a, const uint32_t* b) {
    asm volatile(
        "mma.sync.aligned.m16n8k8.row.col.f32.tf32.tf32.f32 "
        "{%0,%1,%2,%3}, {%4,%5,%6,%7}, {%8,%9}, {%0,%1,%2,%3};"
        : "+f"(c[0]), "+f"(c[1]), "+f"(c[2]), "+f"(c[3])
        : "r"(a[0]), "r"(a[1]), "r"(a[2]), "r"(a[3]), "r"(b[0]), "r"(b[1]));
}

// ---------------- zero scratch for one graph ----------------
__global__ void k_zero() {
    int stride = gridDim.x * blockDim.x;
    int i0 = blockIdx.x * blockDim.x + threadIdx.x;
    float4 z4 = make_float4(0.f, 0.f, 0.f, 0.f);
    float4* a1 = (float4*)g_agg1;
    float4* a2 = (float4*)g_agg2;
    const int n4 = NN * D / 4;
    for (int i = i0; i < n4; i += stride) { a1[i] = z4; a2[i] = z4; }
    for (int i = i0; i < NN; i += stride) { g_dego[i] = 0; g_degi[i] = 0; }
}

// ---------------- weight transpose + tf32 pre-round (once) ----------------
__global__ void k_prep(const float* __restrict__ W1, const float* __restrict__ W2,
                       const float* __restrict__ W3, const float* __restrict__ W4) {
    int i = blockIdx.x * blockDim.x + threadIdx.x;
    if (i < 128 * 256) {                       // W1: [128,256] -> Wt1 [256,128]
        int k = i / 256, n = i % 256;
        g_Wt1[n * 128 + k] = tf32r(W1[i]);
    } else if (i < 2 * 128 * 256) {            // W2: [256,128] -> Wt2 [128,256]
        int j = i - 128 * 256;
        int k = j / 128, n = j % 128;
        g_Wt2[n * 256 + k] = tf32r(W2[j]);
    } else if (i < 2 * 128 * 256 + 128 * 128) {  // W3 (fc1)
        int j = i - 2 * 128 * 256;
        int k = j / 128, n = j % 128;
        g_Wt3[n * 128 + k] = tf32r(W3[j]);
    } else if (i < 2 * 128 * 256 + 2 * 128 * 128) {  // W4 (fc2)
        int j = i - 2 * 128 * 256 - 128 * 128;
        int k = j / 128, n = j % 128;
        g_Wt4[n * 128 + k] = tf32r(W4[j]);
    }
}

// ---------------- degree counting ----------------
__global__ void k_deg(const int* __restrict__ src, const int* __restrict__ dst, int E) {
    int e = blockIdx.x * blockDim.x + threadIdx.x;
    if (e < E) {
        atomicAdd(&g_dego[src[e]], 1);
        atomicAdd(&g_degi[dst[e]], 1);
    }
}

__global__ void k_norm() {
    int i = blockIdx.x * blockDim.x + threadIdx.x;
    if (i < NN) {
        g_ns[i] = rsqrtf(fmaxf((float)g_dego[i], 1.f));
        g_nd[i] = rsqrtf(fmaxf((float)g_degi[i], 1.f));
    }
}

// ---------------- edge scatter: out[dst] += X[src] (*norm_src) ----------------
template<bool SCALE>
__global__ void k_scatter(const float* __restrict__ X, const int* __restrict__ src,
                          const int* __restrict__ dst, float* __restrict__ out, int E) {
    int w = (int)((blockIdx.x * blockDim.x + threadIdx.x) >> 5);
    if (w >= E) return;
    int lane = threadIdx.x & 31;
    int s = __ldg(src + w);
    int d = __ldg(dst + w);
    float4 v = *(const float4*)(X + (size_t)s * D + lane * 4);
    if (SCALE) {
        float f = g_ns[s];
        v.x *= f; v.y *= f; v.z *= f; v.w *= f;
    }
    atomicAdd((float4*)(out + (size_t)d * D + lane * 4), v);
}

// ---------------- h = relu(agg * nd[row] + bias[col]) ----------------
__global__ void k_post(const float* __restrict__ agg, const float* __restrict__ bias,
                       float* __restrict__ out) {
    int i = blockIdx.x * blockDim.x + threadIdx.x;
    if (i >= NN * (D / 4)) return;
    int r  = i >> 5;
    int c4 = (i & 31) * 4;
    float nd = g_nd[r];
    float4 a = ((const float4*)agg)[i];
    float4 b = *(const float4*)(bias + c4);
    float4 o;
    o.x = fmaxf(fmaf(a.x, nd, b.x), 0.f);
    o.y = fmaxf(fmaf(a.y, nd, b.y), 0.f);
    o.z = fmaxf(fmaf(a.z, nd, b.z), 0.f);
    o.w = fmaxf(fmaf(a.w, nd, b.w), 0.f);
    ((float4*)out)[i] = o;
}

// ---------------- mma.sync tf32 GEMM ----------------
// C[M, Nc] = act( ((A * arows?) @ Bt^T) * erows? + bias? )
// A: [M,K] fp32 row-major. Bt: [Nc,K] fp32 row-major, pre tf32-rounded.
// CTA: 256 thr, tile 128x128. Warp tile 32(M)x64(N), m16n8k8 fragments.
// K chunked by 32, cp.async double buffer, smem stride 36 (conflict-free).
#define LDSW 36
#define STAGE_F (128 * LDSW)
template<int ACT, bool ASCALE, bool EPISCALE, bool BIAS>
__global__ void __launch_bounds__(256) k_mgemm(
    const float* __restrict__ A, const float* __restrict__ Bt, float* __restrict__ C,
    int M, int K, int Nc,
    const float* __restrict__ arows, const float* __restrict__ erows,
    const float* __restrict__ bias)
{
    extern __shared__ float sm[];   // [2 stages A | 2 stages B], each 128*36 floats
    uint32_t smbase = smem_u32(sm);

    int tid = threadIdx.x;
    int lane = tid & 31, wid = tid >> 5;
    int g = lane >> 2, tig = lane & 3;
    int warp_m = wid & 3, warp_n = wid >> 2;
    int bm = blockIdx.y * 128;
    int bn = blockIdx.x * 128;

    // loader mapping: 2 threads per row, 16 floats each
    int lrow = tid >> 1;
    int lcol = (tid & 1) * 16;
    bool arv = (bm + lrow) < M;
    const float* gA = A  + (size_t)(arv ? bm + lrow : 0) * K + lcol;
    const float* gB = Bt + (size_t)(bn + lrow) * K + lcol;
    uint32_t sOff = (uint32_t)(lrow * LDSW + lcol) * 4;

    const int nchunks = K >> 5;

    // per-thread A-row scales
    float ascv[4];
    if (ASCALE) {
        #pragma unroll
        for (int i = 0; i < 2; i++)
            #pragma unroll
            for (int h = 0; h < 2; h++) {
                int r = bm + warp_m * 32 + i * 16 + h * 8 + g;
                ascv[i * 2 + h] = (r < M) ? arows[r] : 0.f;
            }
    }

    float acc[2][8][4];
    #pragma unroll
    for (int i = 0; i < 2; i++)
        #pragma unroll
        for (int j = 0; j < 8; j++)
            #pragma unroll
            for (int q = 0; q < 4; q++) acc[i][j][q] = 0.f;

    // issue chunk c into stage c&1
    auto issue = [&](int c) {
        int st = c & 1;
        uint32_t da = smbase + (uint32_t)st * STAGE_F * 4 + sOff;
        uint32_t db = smbase + (uint32_t)(2 + st) * STAGE_F * 4 + sOff;
        const float* pa = gA + c * 32;
        const float* pb = gB + c * 32;
        #pragma unroll
        for (int j = 0; j < 4; j++) cpasync16(da + j * 16, pa + j * 4, arv);
        #pragma unroll
        for (int j = 0; j < 4; j++) cpasync16(db + j * 16, pb + j * 4, true);
        cp_commit();
    };

    issue(0);

    for (int c = 0; c < nchunks; c++) {
        if (c + 1 < nchunks) {
            issue(c + 1);
            asm volatile("cp.async.wait_group 1;" ::: "memory");
        } else {
            asm volatile("cp.async.wait_group 0;" ::: "memory");
        }
        __syncthreads();

        const float* As = sm + (c & 1) * STAGE_F;
        const float* Bs = sm + (2 + (c & 1)) * STAGE_F;

        #pragma unroll
        for (int s = 0; s < 4; s++) {
            int k0 = s * 8;
            // A fragments (scale + round to tf32)
            uint32_t af[2][4];
            #pragma unroll
            for (int i = 0; i < 2; i++) {
                int rb = warp_m * 32 + i * 16 + g;
                float a0 = As[rb * LDSW + k0 + tig];
                float a1 = As[(rb + 8) * LDSW + k0 + tig];
                float a2 = As[rb * LDSW + k0 + tig + 4];
                float a3 = As[(rb + 8) * LDSW + k0 + tig + 4];
                if (ASCALE) {
                    a0 *= ascv[i * 2];     a2 *= ascv[i * 2];
                    a1 *= ascv[i * 2 + 1]; a3 *= ascv[i * 2 + 1];
                }
                af[i][0] = __float_as_uint(tf32r(a0));
                af[i][1] = __float_as_uint(tf32r(a1));
                af[i][2] = __float_as_uint(tf32r(a2));
                af[i][3] = __float_as_uint(tf32r(a3));
            }
            // B fragments (pre-rounded)
            uint32_t bf[8][2];
            #pragma unroll
            for (int j = 0; j < 8; j++) {
                int nb = warp_n * 64 + j * 8 + g;
                bf[j][0] = __float_as_uint(Bs[nb * LDSW + k0 + tig]);
                bf[j][1] = __float_as_uint(Bs[nb * LDSW + k0 + tig + 4]);
            }
            #pragma unroll
            for (int i = 0; i < 2; i++)
                #pragma unroll
                for (int j = 0; j < 8; j++)
                    mma_tf32(acc[i][j], af[i], bf[j]);
        }
        __syncthreads();
    }

    // epilogue
    #pragma unroll
    for (int i = 0; i < 2; i++) {
        int r0 = bm + warp_m * 32 + i * 16 + g;
        int r1 = r0 + 8;
        bool v0 = r0 < M, v1 = r1 < M;
        float es0 = 1.f, es1 = 1.f;
        if (EPISCALE) {
            es0 = v0 ? erows[r0] : 0.f;
            es1 = v1 ? erows[r1] : 0.f;
        }
        #pragma unroll
        for (int j = 0; j < 8; j++) {
            int cb = bn + warp_n * 64 + j * 8 + 2 * tig;
            float2 bb = make_float2(0.f, 0.f);
            if (BIAS) bb = *(const float2*)(bias + cb);
            float o0 = acc[i][j][0] * es0 + bb.x;
            float o1 = acc[i][j][1] * es0 + bb.y;
            float o2 = acc[i][j][2] * es1 + bb.x;
            float o3 = acc[i][j][3] * es1 + bb.y;
            if (ACT == 1) {
                o0 = fmaxf(o0, 0.f); o1 = fmaxf(o1, 0.f);
                o2 = fmaxf(o2, 0.f); o3 = fmaxf(o3, 0.f);
            } else if (ACT == 2) {
                o0 = (o0 > 0.f) ? o0 : expm1f(o0);
                o1 = (o1 > 0.f) ? o1 : expm1f(o1);
                o2 = (o2 > 0.f) ? o2 : expm1f(o2);
                o3 = (o3 > 0.f) ? o3 : expm1f(o3);
            }
            if (v0) *(float2*)(C + (size_t)r0 * Nc + cb) = make_float2(o0, o1);
            if (v1) *(float2*)(C + (size_t)r1 * Nc + cb) = make_float2(o2, o3);
        }
    }
}

// ---------------- driver ----------------
extern "C" void kernel_launch(void* const* d_in, const int* in_sizes, int n_in,
                              void* d_out, int out_size) {
    const float* feat1 = (const float*)d_in[0];
    const float* feat2 = (const float*)d_in[1];
    const int*   ei1   = (const int*)d_in[2];
    const int*   ei2   = (const int*)d_in[3];
    const float* W1    = (const float*)d_in[4];
    const float* b1    = (const float*)d_in[5];
    const float* W2    = (const float*)d_in[6];
    const float* b2    = (const float*)d_in[7];
    const float* f1W   = (const float*)d_in[8];
    const float* f1b   = (const float*)d_in[9];
    const float* f2W   = (const float*)d_in[10];
    const float* f2b   = (const float*)d_in[11];
    int E1 = in_sizes[2] / 2;
    int E2 = in_sizes[3] / 2;
    float* out = (float*)d_out;

    float *agg1, *l1, *m, *agg2, *h, *z, *ns, *nd;
    float *wt1, *wt2, *wt3, *wt4;
    cudaGetSymbolAddress((void**)&agg1, g_agg1);
    cudaGetSymbolAddress((void**)&l1,   g_l1);
    cudaGetSymbolAddress((void**)&m,    g_m);
    cudaGetSymbolAddress((void**)&agg2, g_agg2);
    cudaGetSymbolAddress((void**)&h,    g_h);
    cudaGetSymbolAddress((void**)&z,    g_z);
    cudaGetSymbolAddress((void**)&ns,   g_ns);
    cudaGetSymbolAddress((void**)&nd,   g_nd);
    cudaGetSymbolAddress((void**)&wt1,  g_Wt1);
    cudaGetSymbolAddress((void**)&wt2,  g_Wt2);
    cudaGetSymbolAddress((void**)&wt3,  g_Wt3);
    cudaGetSymbolAddress((void**)&wt4,  g_Wt4);

    const int SMEM = 4 * STAGE_F * 4;  // 73728 bytes
    cudaFuncSetAttribute(k_mgemm<1, false, true, true>,
                         cudaFuncAttributeMaxDynamicSharedMemorySize, SMEM);
    cudaFuncSetAttribute(k_mgemm<0, true, false, false>,
                         cudaFuncAttributeMaxDynamicSharedMemorySize, SMEM);
    cudaFuncSetAttribute(k_mgemm<2, false, false, true>,
                         cudaFuncAttributeMaxDynamicSharedMemorySize, SMEM);
    cudaFuncSetAttribute(k_mgemm<0, false, false, true>,
                         cudaFuncAttributeMaxDynamicSharedMemorySize, SMEM);

    int mtiles = (NN + 127) / 128;

    k_prep<<<(2 * 128 * 256 + 2 * 128 * 128 + 255) / 256, 256>>>(W1, W2, f1W, f2W);

    for (int g = 0; g < 2; g++) {
        const float* feat = g ? feat2 : feat1;
        const int*   ei   = g ? ei2 : ei1;
        int E = g ? E2 : E1;
        const int* src = ei;
        const int* dst = ei + E;
        float* outg = out + (size_t)g * NN * D;

        k_zero<<<2048, 256>>>();
        k_deg<<<(E + 255) / 256, 256>>>(src, dst, E);
        k_norm<<<(NN + 255) / 256, 256>>>();

        // layer 1: agg1[dst] += feat[src] * ns[src]
        k_scatter<true><<<(E * 32 + 255) / 256, 256>>>(feat, src, dst, agg1, E);
        // l1 = relu((agg1 @ W1) * nd + b1)
        k_mgemm<1, false, true, true><<<dim3(2, mtiles), 256, SMEM>>>(
            agg1, wt1, l1, NN, 128, 256, nullptr, nd, b1);

        // layer 2: m = (l1 * ns) @ W2, then scatter, then post
        k_mgemm<0, true, false, false><<<dim3(1, mtiles), 256, SMEM>>>(
            l1, wt2, m, NN, 256, 128, ns, nullptr, nullptr);
        k_scatter<false><<<(E * 32 + 255) / 256, 256>>>(m, src, dst, agg2, E);
        k_post<<<(NN * 32 + 255) / 256, 256>>>(agg2, b2, h);

        // projection MLP
        k_mgemm<2, false, false, true><<<dim3(1, mtiles), 256, SMEM>>>(
            h, wt3, z, NN, 128, 128, nullptr, nullptr, f1b);
        k_mgemm<0, false, false, true><<<dim3(1, mtiles), 256, SMEM>>>(
            z, wt4, outg, NN, 128, 128, nullptr, nullptr, f2b);
    }
}

// round 4
// speedup vs baseline: 1.8875x; 1.1272x over previous
#include <cuda_runtime.h>
#include <math.h>
#include <stdint.h>

#define NN 50000
#define D  128
#define H2 256
#define EMAX 1000000

// ---------------- scratch (no allocations allowed) ----------------
__device__ float g_agg1[NN * D];
__device__ float g_l1 [NN * H2];
__device__ float g_m  [NN * D];
__device__ float g_h  [NN * D];
__device__ float g_z  [NN * D];
__device__ float g_ns [NN];
__device__ float g_nd [NN];
__device__ int   g_dego[NN];
__device__ int   g_degi[NN];
__device__ int   g_off [NN + 1];
__device__ int   g_cur [NN];
__device__ int   g_csr [EMAX];
// transposed ([N,K] row-major) + tf32-rounded weights
__device__ float g_Wt1[256 * 128];
__device__ float g_Wt2[128 * 256];
__device__ float g_Wt3[128 * 128];
__device__ float g_Wt4[128 * 128];

// ---------------- helpers ----------------
__device__ __forceinline__ uint32_t smem_u32(const void* p) {
    uint32_t a;
    asm("{ .reg .u64 t; cvta.to.shared.u64 t, %1; cvt.u32.u64 %0, t; }" : "=r"(a) : "l"(p));
    return a;
}
__device__ __forceinline__ float tf32r(float x) {
    uint32_t u;
    asm("cvt.rna.tf32.f32 %0, %1;" : "=r"(u) : "f"(x));
    return __uint_as_float(u);
}
__device__ __forceinline__ void cpasync16(uint32_t saddr, const void* gaddr, bool pred) {
    int sz = pred ? 16 : 0;
    asm volatile("cp.async.ca.shared.global [%0], [%1], 16, %2;"
                 :: "r"(saddr), "l"(gaddr), "r"(sz) : "memory");
}
__device__ __forceinline__ void cp_commit() {
    asm volatile("cp.async.commit_group;" ::: "memory");
}
__device__ __forceinline__ void mma_tf32(float* c, const uint32_t* a, const uint32_t* b) {
    asm volatile(
        "mma.sync.aligned.m16n8k8.row.col.f32.tf32.tf32.f32 "
        "{%0,%1,%2,%3}, {%4,%5,%6,%7}, {%8,%9}, {%0,%1,%2,%3};"
        : "+f"(c[0]), "+f"(c[1]), "+f"(c[2]), "+f"(c[3])
        : "r"(a[0]), "r"(a[1]), "r"(a[2]), "r"(a[3]), "r"(b[0]), "r"(b[1]));
}

// ---------------- per-graph init: zero degrees ----------------
__global__ void k_zerodeg() {
    int i = blockIdx.x * blockDim.x + threadIdx.x;
    if (i < NN) { g_dego[i] = 0; g_degi[i] = 0; }
}

// ---------------- weight transpose + tf32 pre-round (once) ----------------
__global__ void k_prep(const float* __restrict__ W1, const float* __restrict__ W2,
                       const float* __restrict__ W3, const float* __restrict__ W4) {
    int i = blockIdx.x * blockDim.x + threadIdx.x;
    if (i < 128 * 256) {
        int k = i / 256, n = i % 256;
        g_Wt1[n * 128 + k] = tf32r(W1[i]);
    } else if (i < 2 * 128 * 256) {
        int j = i - 128 * 256;
        int k = j / 128, n = j % 128;
        g_Wt2[n * 256 + k] = tf32r(W2[j]);
    } else if (i < 2 * 128 * 256 + 128 * 128) {
        int j = i - 2 * 128 * 256;
        int k = j / 128, n = j % 128;
        g_Wt3[n * 128 + k] = tf32r(W3[j]);
    } else if (i < 2 * 128 * 256 + 2 * 128 * 128) {
        int j = i - 2 * 128 * 256 - 128 * 128;
        int k = j / 128, n = j % 128;
        g_Wt4[n * 128 + k] = tf32r(W4[j]);
    }
}

// ---------------- degree counting ----------------
__global__ void k_deg(const int* __restrict__ src, const int* __restrict__ dst, int E) {
    int e = blockIdx.x * blockDim.x + threadIdx.x;
    if (e < E) {
        atomicAdd(&g_dego[src[e]], 1);
        atomicAdd(&g_degi[dst[e]], 1);
    }
}

__global__ void k_norm() {
    int i = blockIdx.x * blockDim.x + threadIdx.x;
    if (i < NN) {
        g_ns[i] = rsqrtf(fmaxf((float)g_dego[i], 1.f));
        g_nd[i] = rsqrtf(fmaxf((float)g_degi[i], 1.f));
    }
}

// ---------------- exclusive scan of in-degrees -> g_off, g_cur ----------------
__global__ void __launch_bounds__(1024) k_scan() {
    __shared__ int ss[1024];
    int t = threadIdx.x;
    const int CH = (NN + 1023) >> 10;       // 49
    int lo = t * CH;
    int hi = lo + CH; if (hi > NN) hi = NN;
    int s = 0;
    for (int i = lo; i < hi; i++) s += g_degi[i];
    ss[t] = s;
    __syncthreads();
    // Hillis-Steele inclusive scan
    for (int off = 1; off < 1024; off <<= 1) {
        int v = (t >= off) ? ss[t - off] : 0;
        __syncthreads();
        ss[t] += v;
        __syncthreads();
    }
    int run = (t == 0) ? 0 : ss[t - 1];
    for (int i = lo; i < hi; i++) {
        g_off[i] = run; g_cur[i] = run;
        run += g_degi[i];
    }
    if (t == 1023) g_off[NN] = ss[1023];
}

// ---------------- CSR fill: bucket src indices by dst ----------------
__global__ void k_fill(const int* __restrict__ src, const int* __restrict__ dst, int E) {
    int e = blockIdx.x * blockDim.x + threadIdx.x;
    if (e < E) {
        int d = dst[e];
        int p = atomicAdd(&g_cur[d], 1);
        g_csr[p] = src[e];
    }
}

// ---------------- CSR gather: out[n] = sum_{e in in(n)} X[src_e] (*ns[src_e]) ----------------
// warp per node; POST: out = relu(acc * nd[n] + bias)
template<bool SCALE, bool POST>
__global__ void k_gather(const float* __restrict__ X, float* __restrict__ out,
                         const float* __restrict__ bias) {
    int warp = (int)((blockIdx.x * blockDim.x + threadIdx.x) >> 5);
    if (warp >= NN) return;
    int lane = threadIdx.x & 31;
    int start = g_off[warp];
    int end   = g_off[warp + 1];

    float4 acc0 = make_float4(0.f, 0.f, 0.f, 0.f);
    float4 acc1 = make_float4(0.f, 0.f, 0.f, 0.f);

    int e = start;
    #pragma unroll 2
    for (; e + 1 < end; e += 2) {
        int s0 = __ldg(g_csr + e);
        int s1 = __ldg(g_csr + e + 1);
        float4 v0 = *(const float4*)(X + (size_t)s0 * D + lane * 4);
        float4 v1 = *(const float4*)(X + (size_t)s1 * D + lane * 4);
        float f0 = 1.f, f1 = 1.f;
        if (SCALE) { f0 = __ldg(g_ns + s0); f1 = __ldg(g_ns + s1); }
        acc0.x = fmaf(v0.x, f0, acc0.x); acc0.y = fmaf(v0.y, f0, acc0.y);
        acc0.z = fmaf(v0.z, f0, acc0.z); acc0.w = fmaf(v0.w, f0, acc0.w);
        acc1.x = fmaf(v1.x, f1, acc1.x); acc1.y = fmaf(v1.y, f1, acc1.y);
        acc1.z = fmaf(v1.z, f1, acc1.z); acc1.w = fmaf(v1.w, f1, acc1.w);
    }
    if (e < end) {
        int s0 = __ldg(g_csr + e);
        float4 v0 = *(const float4*)(X + (size_t)s0 * D + lane * 4);
        float f0 = SCALE ? __ldg(g_ns + s0) : 1.f;
        acc0.x = fmaf(v0.x, f0, acc0.x); acc0.y = fmaf(v0.y, f0, acc0.y);
        acc0.z = fmaf(v0.z, f0, acc0.z); acc0.w = fmaf(v0.w, f0, acc0.w);
    }
    acc0.x += acc1.x; acc0.y += acc1.y; acc0.z += acc1.z; acc0.w += acc1.w;

    if (POST) {
        float nd = g_nd[warp];
        float4 b = *(const float4*)(bias + lane * 4);
        acc0.x = fmaxf(fmaf(acc0.x, nd, b.x), 0.f);
        acc0.y = fmaxf(fmaf(acc0.y, nd, b.y), 0.f);
        acc0.z = fmaxf(fmaf(acc0.z, nd, b.z), 0.f);
        acc0.w = fmaxf(fmaf(acc0.w, nd, b.w), 0.f);
    }
    *(float4*)(out + (size_t)warp * D + lane * 4) = acc0;
}

// ---------------- mma.sync tf32 GEMM (unchanged from R3) ----------------
#define LDSW 36
#define STAGE_F (128 * LDSW)
template<int ACT, bool ASCALE, bool EPISCALE, bool BIAS>
__global__ void __launch_bounds__(256) k_mgemm(
    const float* __restrict__ A, const float* __restrict__ Bt, float* __restrict__ C,
    int M, int K, int Nc,
    const float* __restrict__ arows, const float* __restrict__ erows,
    const float* __restrict__ bias)
{
    extern __shared__ float sm[];
    int tid = threadIdx.x;
    int lane = tid & 31, wid = tid >> 5;
    int g = lane >> 2, tig = lane & 3;
    int warp_m = wid & 3, warp_n = wid >> 2;
    int bm = blockIdx.y * 128;
    int bn = blockIdx.x * 128;
    uint32_t smbase = smem_u32(sm);

    int lrow = tid >> 1;
    int lcol = (tid & 1) * 16;
    bool arv = (bm + lrow) < M;
    const float* gA = A  + (size_t)(arv ? bm + lrow : 0) * K + lcol;
    const float* gB = Bt + (size_t)(bn + lrow) * K + lcol;
    uint32_t sOff = (uint32_t)(lrow * LDSW + lcol) * 4;

    const int nchunks = K >> 5;

    float ascv[4];
    if (ASCALE) {
        #pragma unroll
        for (int i = 0; i < 2; i++)
            #pragma unroll
            for (int h = 0; h < 2; h++) {
                int r = bm + warp_m * 32 + i * 16 + h * 8 + g;
                ascv[i * 2 + h] = (r < M) ? arows[r] : 0.f;
            }
    }

    float acc[2][8][4];
    #pragma unroll
    for (int i = 0; i < 2; i++)
        #pragma unroll
        for (int j = 0; j < 8; j++)
            #pragma unroll
            for (int q = 0; q < 4; q++) acc[i][j][q] = 0.f;

    auto issue = [&](int c) {
        int st = c & 1;
        uint32_t da = smbase + (uint32_t)st * STAGE_F * 4 + sOff;
        uint32_t db = smbase + (uint32_t)(2 + st) * STAGE_F * 4 + sOff;
        const float* pa = gA + c * 32;
        const float* pb = gB + c * 32;
        #pragma unroll
        for (int j = 0; j < 4; j++) cpasync16(da + j * 16, pa + j * 4, arv);
        #pragma unroll
        for (int j = 0; j < 4; j++) cpasync16(db + j * 16, pb + j * 4, true);
        cp_commit();
    };

    issue(0);

    for (int c = 0; c < nchunks; c++) {
        if (c + 1 < nchunks) {
            issue(c + 1);
            asm volatile("cp.async.wait_group 1;" ::: "memory");
        } else {
            asm volatile("cp.async.wait_group 0;" ::: "memory");
        }
        __syncthreads();

        const float* As = sm + (c & 1) * STAGE_F;
        const float* Bs = sm + (2 + (c & 1)) * STAGE_F;

        #pragma unroll
        for (int s = 0; s < 4; s++) {
            int k0 = s * 8;
            uint32_t af[2][4];
            #pragma unroll
            for (int i = 0; i < 2; i++) {
                int rb = warp_m * 32 + i * 16 + g;
                float a0 = As[rb * LDSW + k0 + tig];
                float a1 = As[(rb + 8) * LDSW + k0 + tig];
                float a2 = As[rb * LDSW + k0 + tig + 4];
                float a3 = As[(rb + 8) * LDSW + k0 + tig + 4];
                if (ASCALE) {
                    a0 *= ascv[i * 2];     a2 *= ascv[i * 2];
                    a1 *= ascv[i * 2 + 1]; a3 *= ascv[i * 2 + 1];
                }
                af[i][0] = __float_as_uint(tf32r(a0));
                af[i][1] = __float_as_uint(tf32r(a1));
                af[i][2] = __float_as_uint(tf32r(a2));
                af[i][3] = __float_as_uint(tf32r(a3));
            }
            uint32_t bf[8][2];
            #pragma unroll
            for (int j = 0; j < 8; j++) {
                int nb = warp_n * 64 + j * 8 + g;
                bf[j][0] = __float_as_uint(Bs[nb * LDSW + k0 + tig]);
                bf[j][1] = __float_as_uint(Bs[nb * LDSW + k0 + tig + 4]);
            }
            #pragma unroll
            for (int i = 0; i < 2; i++)
                #pragma unroll
                for (int j = 0; j < 8; j++)
                    mma_tf32(acc[i][j], af[i], bf[j]);
        }
        __syncthreads();
    }

    #pragma unroll
    for (int i = 0; i < 2; i++) {
        int r0 = bm + warp_m * 32 + i * 16 + g;
        int r1 = r0 + 8;
        bool v0 = r0 < M, v1 = r1 < M;
        float es0 = 1.f, es1 = 1.f;
        if (EPISCALE) {
            es0 = v0 ? erows[r0] : 0.f;
            es1 = v1 ? erows[r1] : 0.f;
        }
        #pragma unroll
        for (int j = 0; j < 8; j++) {
            int cb = bn + warp_n * 64 + j * 8 + 2 * tig;
            float2 bb = make_float2(0.f, 0.f);
            if (BIAS) bb = *(const float2*)(bias + cb);
            float o0 = acc[i][j][0] * es0 + bb.x;
            float o1 = acc[i][j][1] * es0 + bb.y;
            float o2 = acc[i][j][2] * es1 + bb.x;
            float o3 = acc[i][j][3] * es1 + bb.y;
            if (ACT == 1) {
                o0 = fmaxf(o0, 0.f); o1 = fmaxf(o1, 0.f);
                o2 = fmaxf(o2, 0.f); o3 = fmaxf(o3, 0.f);
            } else if (ACT == 2) {
                o0 = (o0 > 0.f) ? o0 : expm1f(o0);
                o1 = (o1 > 0.f) ? o1 : expm1f(o1);
                o2 = (o2 > 0.f) ? o2 : expm1f(o2);
                o3 = (o3 > 0.f) ? o3 : expm1f(o3);
            }
            if (v0) *(float2*)(C + (size_t)r0 * Nc + cb) = make_float2(o0, o1);
            if (v1) *(float2*)(C + (size_t)r1 * Nc + cb) = make_float2(o2, o3);
        }
    }
}

// ---------------- driver ----------------
extern "C" void kernel_launch(void* const* d_in, const int* in_sizes, int n_in,
                              void* d_out, int out_size) {
    const float* feat1 = (const float*)d_in[0];
    const float* feat2 = (const float*)d_in[1];
    const int*   ei1   = (const int*)d_in[2];
    const int*   ei2   = (const int*)d_in[3];
    const float* W1    = (const float*)d_in[4];
    const float* b1    = (const float*)d_in[5];
    const float* W2    = (const float*)d_in[6];
    const float* b2    = (const float*)d_in[7];
    const float* f1W   = (const float*)d_in[8];
    const float* f1b   = (const float*)d_in[9];
    const float* f2W   = (const float*)d_in[10];
    const float* f2b   = (const float*)d_in[11];
    int E1 = in_sizes[2] / 2;
    int E2 = in_sizes[3] / 2;
    float* out = (float*)d_out;

    float *agg1, *l1, *m, *h, *z, *ns, *nd;
    float *wt1, *wt2, *wt3, *wt4;
    cudaGetSymbolAddress((void**)&agg1, g_agg1);
    cudaGetSymbolAddress((void**)&l1,   g_l1);
    cudaGetSymbolAddress((void**)&m,    g_m);
    cudaGetSymbolAddress((void**)&h,    g_h);
    cudaGetSymbolAddress((void**)&z,    g_z);
    cudaGetSymbolAddress((void**)&ns,   g_ns);
    cudaGetSymbolAddress((void**)&nd,   g_nd);
    cudaGetSymbolAddress((void**)&wt1,  g_Wt1);
    cudaGetSymbolAddress((void**)&wt2,  g_Wt2);
    cudaGetSymbolAddress((void**)&wt3,  g_Wt3);
    cudaGetSymbolAddress((void**)&wt4,  g_Wt4);

    const int SMEM = 4 * STAGE_F * 4;  // 73728 bytes
    cudaFuncSetAttribute(k_mgemm<1, false, true, true>,
                         cudaFuncAttributeMaxDynamicSharedMemorySize, SMEM);
    cudaFuncSetAttribute(k_mgemm<0, true, false, false>,
                         cudaFuncAttributeMaxDynamicSharedMemorySize, SMEM);
    cudaFuncSetAttribute(k_mgemm<2, false, false, true>,
                         cudaFuncAttributeMaxDynamicSharedMemorySize, SMEM);
    cudaFuncSetAttribute(k_mgemm<0, false, false, true>,
                         cudaFuncAttributeMaxDynamicSharedMemorySize, SMEM);

    int mtiles = (NN + 127) / 128;
    int gwarp  = (NN * 32 + 255) / 256;

    k_prep<<<(2 * 128 * 256 + 2 * 128 * 128 + 255) / 256, 256>>>(W1, W2, f1W, f2W);

    for (int g = 0; g < 2; g++) {
        const float* feat = g ? feat2 : feat1;
        const int*   ei   = g ? ei2 : ei1;
        int E = g ? E2 : E1;
        const int* src = ei;
        const int* dst = ei + E;
        float* outg = out + (size_t)g * NN * D;

        // degrees + norms + CSR (by dst)
        k_zerodeg<<<(NN + 255) / 256, 256>>>();
        k_deg<<<(E + 255) / 256, 256>>>(src, dst, E);
        k_norm<<<(NN + 255) / 256, 256>>>();
        k_scan<<<1, 1024>>>();
        k_fill<<<(E + 255) / 256, 256>>>(src, dst, E);

        // layer 1: agg1[n] = sum_in feat[src]*ns[src]; l1 = relu((agg1@W1)*nd + b1)
        k_gather<true, false><<<gwarp, 256>>>(feat, agg1, nullptr);
        k_mgemm<1, false, true, true><<<dim3(2, mtiles), 256, SMEM>>>(
            agg1, wt1, l1, NN, 128, 256, nullptr, nd, b1);

        // layer 2: m = (l1*ns)@W2; h = relu(gather(m)*nd + b2)
        k_mgemm<0, true, false, false><<<dim3(1, mtiles), 256, SMEM>>>(
            l1, wt2, m, NN, 256, 128, ns, nullptr, nullptr);
        k_gather<false, true><<<gwarp, 256>>>(m, h, b2);

        // projection MLP
        k_mgemm<2, false, false, true><<<dim3(1, mtiles), 256, SMEM>>>(
            h, wt3, z, NN, 128, 128, nullptr, nullptr, f1b);
        k_mgemm<0, false, false, true><<<dim3(1, mtiles), 256, SMEM>>>(
            z, wt4, outg, NN, 128, 128, nullptr, nullptr, f2b);
    }
}

// round 5
// speedup vs baseline: 2.1607x; 1.1447x over previous
#include <cuda_runtime.h>
#include <math.h>
#include <stdint.h>

#define NN 50000
#define N2 (2 * NN)
#define D  128
#define H2 256
#define EMAX 1000000

// ---------------- scratch (no allocations allowed) ----------------
__device__ float g_agg1[N2 * D];
__device__ float g_l1 [N2 * H2];
__device__ float g_m  [N2 * D];
__device__ float g_h  [N2 * D];
__device__ float g_z  [N2 * D];
__device__ float g_ns [N2];
__device__ float g_nd [N2];
__device__ int   g_dego[N2];
__device__ int   g_degi[N2];
__device__ int   g_off [2 * (NN + 1)];
__device__ int   g_cur [N2];
__device__ int   g_csr [2 * EMAX];
// transposed ([N,K] row-major) + tf32-rounded weights
__device__ float g_Wt1[256 * 128];
__device__ float g_Wt2[128 * 256];
__device__ float g_Wt3[128 * 128];
__device__ float g_Wt4[128 * 128];

// ---------------- helpers ----------------
__device__ __forceinline__ uint32_t smem_u32(const void* p) {
    uint32_t a;
    asm("{ .reg .u64 t; cvta.to.shared.u64 t, %1; cvt.u32.u64 %0, t; }" : "=r"(a) : "l"(p));
    return a;
}
__device__ __forceinline__ float tf32r(float x) {
    uint32_t u;
    asm("cvt.rna.tf32.f32 %0, %1;" : "=r"(u) : "f"(x));
    return __uint_as_float(u);
}
__device__ __forceinline__ void cpasync16(uint32_t saddr, const void* gaddr, bool pred) {
    int sz = pred ? 16 : 0;
    asm volatile("cp.async.ca.shared.global [%0], [%1], 16, %2;"
                 :: "r"(saddr), "l"(gaddr), "r"(sz) : "memory");
}
__device__ __forceinline__ void cp_commit() {
    asm volatile("cp.async.commit_group;" ::: "memory");
}
__device__ __forceinline__ void mma_tf32(float* c, const uint32_t* a, const uint32_t* b) {
    asm volatile(
        "mma.sync.aligned.m16n8k8.row.col.f32.tf32.tf32.f32 "
        "{%0,%1,%2,%3}, {%4,%5,%6,%7}, {%8,%9}, {%0,%1,%2,%3};"
        : "+f"(c[0]), "+f"(c[1]), "+f"(c[2]), "+f"(c[3])
        : "r"(a[0]), "r"(a[1]), "r"(a[2]), "r"(a[3]), "r"(b[0]), "r"(b[1]));
}
__device__ __forceinline__ void fma4(float4& acc, float4 v, float f) {
    acc.x = fmaf(v.x, f, acc.x); acc.y = fmaf(v.y, f, acc.y);
    acc.z = fmaf(v.z, f, acc.z); acc.w = fmaf(v.w, f, acc.w);
}

// ---------------- zero degrees (both graphs) ----------------
__global__ void k_zerodeg() {
    int i = blockIdx.x * blockDim.x + threadIdx.x;
    if (i < N2) { g_dego[i] = 0; g_degi[i] = 0; }
}

// ---------------- weight transpose + tf32 pre-round (once) ----------------
__global__ void k_prep(const float* __restrict__ W1, const float* __restrict__ W2,
                       const float* __restrict__ W3, const float* __restrict__ W4) {
    int i = blockIdx.x * blockDim.x + threadIdx.x;
    if (i < 128 * 256) {
        int k = i / 256, n = i % 256;
        g_Wt1[n * 128 + k] = tf32r(W1[i]);
    } else if (i < 2 * 128 * 256) {
        int j = i - 128 * 256;
        int k = j / 128, n = j % 128;
        g_Wt2[n * 256 + k] = tf32r(W2[j]);
    } else if (i < 2 * 128 * 256 + 128 * 128) {
        int j = i - 2 * 128 * 256;
        int k = j / 128, n = j % 128;
        g_Wt3[n * 128 + k] = tf32r(W3[j]);
    } else if (i < 2 * 128 * 256 + 2 * 128 * 128) {
        int j = i - 2 * 128 * 256 - 128 * 128;
        int k = j / 128, n = j % 128;
        g_Wt4[n * 128 + k] = tf32r(W4[j]);
    }
}

// ---------------- degree counting (both graphs) ----------------
__global__ void k_deg(const int* __restrict__ s1, const int* __restrict__ d1, int E1,
                      const int* __restrict__ s2, const int* __restrict__ d2, int E2) {
    int e = blockIdx.x * blockDim.x + threadIdx.x;
    if (e < E1) {
        atomicAdd(&g_dego[s1[e]], 1);
        atomicAdd(&g_degi[d1[e]], 1);
    } else if (e < E1 + E2) {
        int j = e - E1;
        atomicAdd(&g_dego[NN + s2[j]], 1);
        atomicAdd(&g_degi[NN + d2[j]], 1);
    }
}

__global__ void k_norm() {
    int i = blockIdx.x * blockDim.x + threadIdx.x;
    if (i < N2) {
        g_ns[i] = rsqrtf(fmaxf((float)g_dego[i], 1.f));
        g_nd[i] = rsqrtf(fmaxf((float)g_degi[i], 1.f));
    }
}

// ---------------- exclusive scan of in-degrees (block per graph) ----------------
__global__ void __launch_bounds__(1024) k_scan() {
    __shared__ int ss[1024];
    int gph = blockIdx.x;
    int t = threadIdx.x;
    const int* deg = g_degi + gph * NN;
    int* off = g_off + gph * (NN + 1);
    int* cur = g_cur + gph * NN;
    const int CH = (NN + 1023) >> 10;
    int lo = t * CH;
    int hi = lo + CH; if (hi > NN) hi = NN;
    int s = 0;
    for (int i = lo; i < hi; i++) s += deg[i];
    ss[t] = s;
    __syncthreads();
    for (int o = 1; o < 1024; o <<= 1) {
        int v = (t >= o) ? ss[t - o] : 0;
        __syncthreads();
        ss[t] += v;
        __syncthreads();
    }
    int run = (t == 0) ? 0 : ss[t - 1];
    for (int i = lo; i < hi; i++) {
        off[i] = run; cur[i] = run;
        run += deg[i];
    }
    if (t == 1023) off[NN] = ss[1023];
}

// ---------------- CSR fill (both graphs) ----------------
__global__ void k_fill(const int* __restrict__ s1, const int* __restrict__ d1, int E1,
                       const int* __restrict__ s2, const int* __restrict__ d2, int E2) {
    int e = blockIdx.x * blockDim.x + threadIdx.x;
    if (e < E1) {
        int p = atomicAdd(&g_cur[d1[e]], 1);
        g_csr[p] = s1[e];
    } else if (e < E1 + E2) {
        int j = e - E1;
        int p = atomicAdd(&g_cur[NN + d2[j]], 1);
        g_csr[EMAX + p] = s2[j];
    }
}

// ---------------- CSR gather (both graphs), warp per node, 4-way MLP ----------------
// out[w] = sum_in X_g[src] (*ns[g*NN+src]);  POST: relu(acc * nd[w] + bias)
template<bool SCALE, bool POST>
__global__ void k_gather(const float* __restrict__ X0, const float* __restrict__ X1,
                         float* __restrict__ out, const float* __restrict__ bias) {
    int w = (int)((blockIdx.x * blockDim.x + threadIdx.x) >> 5);
    if (w >= N2) return;
    int lane = threadIdx.x & 31;
    int gph = (w >= NN) ? 1 : 0;
    int n = w - gph * NN;
    const int* off = g_off + gph * (NN + 1);
    const int* csr = g_csr + gph * EMAX;
    const float* ns = g_ns + gph * NN;
    const float* X = gph ? X1 : X0;
    int start = off[n];
    int end   = off[n + 1];

    float4 a0 = make_float4(0.f, 0.f, 0.f, 0.f);
    float4 a1 = a0, a2 = a0, a3 = a0;

    int e = start;
    for (; e + 3 < end; e += 4) {
        int s0 = __ldg(csr + e), s1 = __ldg(csr + e + 1);
        int s2 = __ldg(csr + e + 2), s3 = __ldg(csr + e + 3);
        float4 v0 = *(const float4*)(X + (size_t)s0 * D + lane * 4);
        float4 v1 = *(const float4*)(X + (size_t)s1 * D + lane * 4);
        float4 v2 = *(const float4*)(X + (size_t)s2 * D + lane * 4);
        float4 v3 = *(const float4*)(X + (size_t)s3 * D + lane * 4);
        float f0 = 1.f, f1 = 1.f, f2 = 1.f, f3 = 1.f;
        if (SCALE) {
            f0 = __ldg(ns + s0); f1 = __ldg(ns + s1);
            f2 = __ldg(ns + s2); f3 = __ldg(ns + s3);
        }
        fma4(a0, v0, f0); fma4(a1, v1, f1); fma4(a2, v2, f2); fma4(a3, v3, f3);
    }
    for (; e < end; e++) {
        int s0 = __ldg(csr + e);
        float4 v0 = *(const float4*)(X + (size_t)s0 * D + lane * 4);
        float f0 = SCALE ? __ldg(ns + s0) : 1.f;
        fma4(a0, v0, f0);
    }
    a0.x += a1.x + a2.x + a3.x;
    a0.y += a1.y + a2.y + a3.y;
    a0.z += a1.z + a2.z + a3.z;
    a0.w += a1.w + a2.w + a3.w;

    if (POST) {
        float nd = g_nd[w];
        float4 b = *(const float4*)(bias + lane * 4);
        a0.x = fmaxf(fmaf(a0.x, nd, b.x), 0.f);
        a0.y = fmaxf(fmaf(a0.y, nd, b.y), 0.f);
        a0.z = fmaxf(fmaf(a0.z, nd, b.z), 0.f);
        a0.w = fmaxf(fmaf(a0.w, nd, b.w), 0.f);
    }
    *(float4*)(out + (size_t)w * D + lane * 4) = a0;
}

// ---------------- mma.sync tf32 GEMM ----------------
#define LDSW 36
#define STAGE_F (128 * LDSW)
template<int ACT, bool ASCALE, bool EPISCALE, bool BIAS>
__global__ void __launch_bounds__(256) k_mgemm(
    const float* __restrict__ A, const float* __restrict__ Bt, float* __restrict__ C,
    int M, int K, int Nc,
    const float* __restrict__ arows, const float* __restrict__ erows,
    const float* __restrict__ bias)
{
    extern __shared__ float sm[];
    int tid = threadIdx.x;
    int lane = tid & 31, wid = tid >> 5;
    int g = lane >> 2, tig = lane & 3;
    int warp_m = wid & 3, warp_n = wid >> 2;
    int bm = blockIdx.y * 128;
    int bn = blockIdx.x * 128;
    uint32_t smbase = smem_u32(sm);

    int lrow = tid >> 1;
    int lcol = (tid & 1) * 16;
    bool arv = (bm + lrow) < M;
    const float* gA = A  + (size_t)(arv ? bm + lrow : 0) * K + lcol;
    const float* gB = Bt + (size_t)(bn + lrow) * K + lcol;
    uint32_t sOff = (uint32_t)(lrow * LDSW + lcol) * 4;

    const int nchunks = K >> 5;

    float ascv[4];
    if (ASCALE) {
        #pragma unroll
        for (int i = 0; i < 2; i++)
            #pragma unroll
            for (int h = 0; h < 2; h++) {
                int r = bm + warp_m * 32 + i * 16 + h * 8 + g;
                ascv[i * 2 + h] = (r < M) ? arows[r] : 0.f;
            }
    }

    float acc[2][8][4];
    #pragma unroll
    for (int i = 0; i < 2; i++)
        #pragma unroll
        for (int j = 0; j < 8; j++)
            #pragma unroll
            for (int q = 0; q < 4; q++) acc[i][j][q] = 0.f;

    auto issue = [&](int c) {
        int st = c & 1;
        uint32_t da = smbase + (uint32_t)st * STAGE_F * 4 + sOff;
        uint32_t db = smbase + (uint32_t)(2 + st) * STAGE_F * 4 + sOff;
        const float* pa = gA + c * 32;
        const float* pb = gB + c * 32;
        #pragma unroll
        for (int j = 0; j < 4; j++) cpasync16(da + j * 16, pa + j * 4, arv);
        #pragma unroll
        for (int j = 0; j < 4; j++) cpasync16(db + j * 16, pb + j * 4, true);
        cp_commit();
    };

    issue(0);

    for (int c = 0; c < nchunks; c++) {
        if (c + 1 < nchunks) {
            issue(c + 1);
            asm volatile("cp.async.wait_group 1;" ::: "memory");
        } else {
            asm volatile("cp.async.wait_group 0;" ::: "memory");
        }
        __syncthreads();

        const float* As = sm + (c & 1) * STAGE_F;
        const float* Bs = sm + (2 + (c & 1)) * STAGE_F;

        #pragma unroll
        for (int s = 0; s < 4; s++) {
            int k0 = s * 8;
            uint32_t af[2][4];
            #pragma unroll
            for (int i = 0; i < 2; i++) {
                int rb = warp_m * 32 + i * 16 + g;
                float a0 = As[rb * LDSW + k0 + tig];
                float a1 = As[(rb + 8) * LDSW + k0 + tig];
                float a2 = As[rb * LDSW + k0 + tig + 4];
                float a3 = As[(rb + 8) * LDSW + k0 + tig + 4];
                if (ASCALE) {
                    a0 *= ascv[i * 2];     a2 *= ascv[i * 2];
                    a1 *= ascv[i * 2 + 1]; a3 *= ascv[i * 2 + 1];
                }
                af[i][0] = __float_as_uint(tf32r(a0));
                af[i][1] = __float_as_uint(tf32r(a1));
                af[i][2] = __float_as_uint(tf32r(a2));
                af[i][3] = __float_as_uint(tf32r(a3));
            }
            uint32_t bf[8][2];
            #pragma unroll
            for (int j = 0; j < 8; j++) {
                int nb = warp_n * 64 + j * 8 + g;
                bf[j][0] = __float_as_uint(Bs[nb * LDSW + k0 + tig]);
                bf[j][1] = __float_as_uint(Bs[nb * LDSW + k0 + tig + 4]);
            }
            #pragma unroll
            for (int i = 0; i < 2; i++)
                #pragma unroll
                for (int j = 0; j < 8; j++)
                    mma_tf32(acc[i][j], af[i], bf[j]);
        }
        __syncthreads();
    }

    #pragma unroll
    for (int i = 0; i < 2; i++) {
        int r0 = bm + warp_m * 32 + i * 16 + g;
        int r1 = r0 + 8;
        bool v0 = r0 < M, v1 = r1 < M;
        float es0 = 1.f, es1 = 1.f;
        if (EPISCALE) {
            es0 = v0 ? erows[r0] : 0.f;
            es1 = v1 ? erows[r1] : 0.f;
        }
        #pragma unroll
        for (int j = 0; j < 8; j++) {
            int cb = bn + warp_n * 64 + j * 8 + 2 * tig;
            float2 bb = make_float2(0.f, 0.f);
            if (BIAS) bb = *(const float2*)(bias + cb);
            float o0 = acc[i][j][0] * es0 + bb.x;
            float o1 = acc[i][j][1] * es0 + bb.y;
            float o2 = acc[i][j][2] * es1 + bb.x;
            float o3 = acc[i][j][3] * es1 + bb.y;
            if (ACT == 1) {
                o0 = fmaxf(o0, 0.f); o1 = fmaxf(o1, 0.f);
                o2 = fmaxf(o2, 0.f); o3 = fmaxf(o3, 0.f);
            } else if (ACT == 2) {
                o0 = (o0 > 0.f) ? o0 : expm1f(o0);
                o1 = (o1 > 0.f) ? o1 : expm1f(o1);
                o2 = (o2 > 0.f) ? o2 : expm1f(o2);
                o3 = (o3 > 0.f) ? o3 : expm1f(o3);
            }
            if (v0) *(float2*)(C + (size_t)r0 * Nc + cb) = make_float2(o0, o1);
            if (v1) *(float2*)(C + (size_t)r1 * Nc + cb) = make_float2(o2, o3);
        }
    }
}

// ---------------- driver ----------------
extern "C" void kernel_launch(void* const* d_in, const int* in_sizes, int n_in,
                              void* d_out, int out_size) {
    const float* feat1 = (const float*)d_in[0];
    const float* feat2 = (const float*)d_in[1];
    const int*   ei1   = (const int*)d_in[2];
    const int*   ei2   = (const int*)d_in[3];
    const float* W1    = (const float*)d_in[4];
    const float* b1    = (const float*)d_in[5];
    const float* W2    = (const float*)d_in[6];
    const float* b2    = (const float*)d_in[7];
    const float* f1W   = (const float*)d_in[8];
    const float* f1b   = (const float*)d_in[9];
    const float* f2W   = (const float*)d_in[10];
    const float* f2b   = (const float*)d_in[11];
    int E1 = in_sizes[2] / 2;
    int E2 = in_sizes[3] / 2;
    float* out = (float*)d_out;

    float *agg1, *l1, *m, *h, *z, *ns, *nd;
    float *wt1, *wt2, *wt3, *wt4;
    cudaGetSymbolAddress((void**)&agg1, g_agg1);
    cudaGetSymbolAddress((void**)&l1,   g_l1);
    cudaGetSymbolAddress((void**)&m,    g_m);
    cudaGetSymbolAddress((void**)&h,    g_h);
    cudaGetSymbolAddress((void**)&z,    g_z);
    cudaGetSymbolAddress((void**)&ns,   g_ns);
    cudaGetSymbolAddress((void**)&nd,   g_nd);
    cudaGetSymbolAddress((void**)&wt1,  g_Wt1);
    cudaGetSymbolAddress((void**)&wt2,  g_Wt2);
    cudaGetSymbolAddress((void**)&wt3,  g_Wt3);
    cudaGetSymbolAddress((void**)&wt4,  g_Wt4);

    const int SMEM = 4 * STAGE_F * 4;  // 73728 bytes
    cudaFuncSetAttribute(k_mgemm<1, false, true, true>,
                         cudaFuncAttributeMaxDynamicSharedMemorySize, SMEM);
    cudaFuncSetAttribute(k_mgemm<0, true, false, false>,
                         cudaFuncAttributeMaxDynamicSharedMemorySize, SMEM);
    cudaFuncSetAttribute(k_mgemm<2, false, false, true>,
                         cudaFuncAttributeMaxDynamicSharedMemorySize, SMEM);
    cudaFuncSetAttribute(k_mgemm<0, false, false, true>,
                         cudaFuncAttributeMaxDynamicSharedMemorySize, SMEM);

    const int* s1 = ei1;
    const int* d1 = ei1 + E1;
    const int* s2 = ei2;
    const int* d2 = ei2 + E2;
    int Etot = E1 + E2;
    int mtiles = (N2 + 127) / 128;          // 782
    int gwarp  = (N2 * 32 + 255) / 256;

    // one-time weight prep
    k_prep<<<(2 * 128 * 256 + 2 * 128 * 128 + 255) / 256, 256>>>(W1, W2, f1W, f2W);

    // CSR build for both graphs
    k_zerodeg<<<(N2 + 255) / 256, 256>>>();
    k_deg<<<(Etot + 255) / 256, 256>>>(s1, d1, E1, s2, d2, E2);
    k_norm<<<(N2 + 255) / 256, 256>>>();
    k_scan<<<2, 1024>>>();
    k_fill<<<(Etot + 255) / 256, 256>>>(s1, d1, E1, s2, d2, E2);

    // layer 1 (batched): agg1 = gather(feat*ns); l1 = relu((agg1@W1)*nd + b1)
    k_gather<true, false><<<gwarp, 256>>>(feat1, feat2, agg1, nullptr);
    k_mgemm<1, false, true, true><<<dim3(2, mtiles), 256, SMEM>>>(
        agg1, wt1, l1, N2, 128, 256, nullptr, nd, b1);

    // layer 2 (batched): m = (l1*ns)@W2; h = relu(gather(m)*nd + b2)
    k_mgemm<0, true, false, false><<<dim3(1, mtiles), 256, SMEM>>>(
        l1, wt2, m, N2, 256, 128, ns, nullptr, nullptr);
    k_gather<false, true><<<gwarp, 256>>>(m, m + (size_t)NN * D, h, b2);

    // projection MLP (batched, final GEMM writes straight to out = [z1; z2])
    k_mgemm<2, false, false, true><<<dim3(1, mtiles), 256, SMEM>>>(
        h, wt3, z, N2, 128, 128, nullptr, nullptr, f1b);
    k_mgemm<0, false, false, true><<<dim3(1, mtiles), 256, SMEM>>>(
        z, wt4, out, N2, 128, 128, nullptr, nullptr, f2b);
}